// round 12
// baseline (speedup 1.0000x reference)
#include <cuda_runtime.h>
#include <math.h>

#define NN   50000
#define EE   500000
#define DD   128
#define BB   50
#define NPG  1000
#define KSEL 500
#define BK   (BB*KSEL)
#define ALPHA_F 0.6f

typedef unsigned long long ull;

#define FMA_F32X2(d, a, b, c) \
    asm("fma.rn.f32x2 %0, %1, %2, %3;" : "=l"(d) : "l"(a), "l"(b), "l"(c))
#define PACK2(d, lo, hi) \
    asm("mov.b64 %0, {%1, %2};" : "=l"(d) : "f"(lo), "f"(hi))
#define UNPACK2(lo, hi, s) \
    asm("mov.b64 {%0, %1}, %2;" : "=f"(lo), "=f"(hi) : "l"(s))

__device__ int   g_deg[NN];
__device__ float g_dinv[NN];
__device__ float g_ds[NN];
__device__ float g_zs[NN];
__device__ float g_sf[NN];
__device__ float g_ssacc[NN];
__device__ int   g_perm[BK];
__device__ float g_selscore[BK];
__device__ int   g_nodemap[NN];
__device__ int   g_off[NN];
__device__ int   g_cursor[NN];
__device__ int   g_csr[EE];
__device__ int   g_total;
__device__ int   g_bsum[512];
__device__ int   g_boff[512];

__global__ void k_deg(const int* __restrict__ dst) {
    int i = blockIdx.x * blockDim.x + threadIdx.x;
    if (i < EE / 4) {
        int4 d4 = ((const int4*)dst)[i];
        atomicAdd(&g_deg[d4.x], 1);
        atomicAdd(&g_deg[d4.y], 1);
        atomicAdd(&g_deg[d4.z], 1);
        atomicAdd(&g_deg[d4.w], 1);
    }
}

__global__ void k_scores(const float* __restrict__ x, const float* __restrict__ Ws,
                         const float* __restrict__ Wf, const float* __restrict__ bf) {
    int warp = (blockIdx.x * blockDim.x + threadIdx.x) >> 5;
    int lane = threadIdx.x & 31;
    if (warp >= NN) return;
    float4 xv = ((const float4*)x)[warp * 32 + lane];
    float4 ws = ((const float4*)Ws)[lane];
    float4 wf = ((const float4*)Wf)[lane];
    float ds = xv.x*ws.x + xv.y*ws.y + xv.z*ws.z + xv.w*ws.w;
    float df = xv.x*wf.x + xv.y*wf.y + xv.z*wf.z + xv.w*wf.w;
    #pragma unroll
    for (int o = 16; o > 0; o >>= 1) {
        ds += __shfl_down_sync(0xffffffffu, ds, o);
        df += __shfl_down_sync(0xffffffffu, df, o);
    }
    if (lane == 0) {
        g_ds[warp] = ds;
        g_sf[warp] = df + bf[0];
    }
}

__global__ void k_offsets() {
    __shared__ int wpref[8];
    int tid = threadIdx.x;
    int n = blockIdx.x * 256 + tid;
    int d = (n < NN) ? g_deg[n] : 0;
    int lane = tid & 31, wid = tid >> 5;
    int v = d;
    #pragma unroll
    for (int o = 1; o < 32; o <<= 1) {
        int u = __shfl_up_sync(0xffffffffu, v, o);
        if (lane >= o) v += u;
    }
    if (lane == 31) wpref[wid] = v;
    __syncthreads();
    if (tid == 0) {
        int t[8], run = 0;
        #pragma unroll
        for (int w = 0; w < 8; w++) { t[w] = run; run += wpref[w]; }
        int base = atomicAdd(&g_total, run);
        #pragma unroll
        for (int w = 0; w < 8; w++) wpref[w] = base + t[w];
    }
    __syncthreads();
    int off = wpref[wid] + (v - d);
    if (n < NN) {
        g_off[n]    = off;
        g_cursor[n] = off;
        float dv = rsqrtf((float)(d + 1));
        g_dinv[n] = dv;
        g_zs[n]   = dv * g_ds[n];
    }
}

// fused: CSR scatter + structure-score scatter in a single edge pass
__global__ void k_csr_score(const int* __restrict__ src, const int* __restrict__ dst) {
    int i = blockIdx.x * blockDim.x + threadIdx.x;
    if (i < EE / 4) {
        int4 s4 = ((const int4*)src)[i];
        int4 d4 = ((const int4*)dst)[i];
        g_csr[atomicAdd(&g_cursor[d4.x], 1)] = s4.x;
        g_csr[atomicAdd(&g_cursor[d4.y], 1)] = s4.y;
        g_csr[atomicAdd(&g_cursor[d4.z], 1)] = s4.z;
        g_csr[atomicAdd(&g_cursor[d4.w], 1)] = s4.w;
        atomicAdd(&g_ssacc[d4.x], g_zs[s4.x]);
        atomicAdd(&g_ssacc[d4.y], g_zs[s4.y]);
        atomicAdd(&g_ssacc[d4.z], g_zs[s4.z]);
        atomicAdd(&g_ssacc[d4.w], g_zs[s4.w]);
    }
}

// fused: score finalization (tanh) + per-graph rank selection
__global__ void k_topk(const float* __restrict__ bs, float* __restrict__ out,
                       long permOff, long batchOff) {
    __shared__ __align__(16) ull sk[NPG];
    __shared__ float ssc[NPG];
    int b = blockIdx.x >> 2;
    int quarter = blockIdx.x & 3;
    int tid = threadIdx.x;
    float bsv = bs[0];
    for (int i = tid; i < NPG; i += 256) {
        int n = b * NPG + i;
        float ss = g_dinv[n] * (g_ssacc[n] + g_zs[n]) + bsv;
        float sc = tanhf(ALPHA_F * ss + (1.0f - ALPHA_F) * g_sf[n]);
        ssc[i] = sc;
        int iv = __float_as_int(sc);
        unsigned u = (unsigned)iv ^ ((unsigned)(iv >> 31) | 0x80000000u);
        sk[i] = ((ull)u << 32) | (unsigned)(~i);
    }
    __syncthreads();
    int j = quarter * 256 + tid;
    if (j >= NPG) return;
    ull myk = sk[j];
    int rank = 0;
    const ulonglong2* p2 = (const ulonglong2*)sk;
    #pragma unroll 4
    for (int i2 = 0; i2 < NPG / 2; i2++) {
        ulonglong2 kv = p2[i2];
        rank += (kv.x > myk);
        rank += (kv.y > myk);
    }
    if (rank < KSEL) {
        int p  = b * NPG + j;
        int gi = b * KSEL + rank;
        g_perm[gi]     = p;
        g_selscore[gi] = ssc[j];
        g_nodemap[p]   = gi;
        out[permOff  + gi] = (float)p;
        out[batchOff + gi] = (float)b;
    }
}

// ---------------- fused gather + FMA2 GEMM ----------------
#define SA_S 132
__global__ void __launch_bounds__(256)
k_gemm(const float* __restrict__ x, const float* __restrict__ W,
       const float* __restrict__ bfu, float* __restrict__ out, long xaeOff) {
    __shared__ __align__(16) float sA[64 * SA_S];   // 33.8 KB
    __shared__ __align__(16) float sB[16 * 128];    // 8 KB

    int tid  = threadIdx.x;
    int lane = tid & 31, wid = tid >> 5;
    int row0 = blockIdx.x * 64;

    #pragma unroll
    for (int i = 0; i < 8; i++) {
        int r = wid * 8 + i;
        int grow = row0 + r;
        float4 acc = make_float4(0.f, 0.f, 0.f, 0.f);
        if (grow < BK) {
            int   p   = g_perm[grow];
            float dvp = g_dinv[p];
            float4 xv = ((const float4*)x)[p * 32 + lane];
            acc = make_float4(dvp*xv.x, dvp*xv.y, dvp*xv.z, dvp*xv.w);
            int beg = g_off[p], len = g_deg[p];
            for (int base = 0; base < len; base += 32) {
                int idx = base + lane;
                int   s  = (idx < len) ? g_csr[beg + idx] : 0;
                float dv = (idx < len) ? g_dinv[s] : 0.f;
                int cnt = min(32, len - base);
                for (int j = 0; j < cnt; j++) {
                    int   sj = __shfl_sync(0xffffffffu, s,  j);
                    float dj = __shfl_sync(0xffffffffu, dv, j);
                    float4 xs = ((const float4*)x)[sj * 32 + lane];
                    acc.x += dj * xs.x;
                    acc.y += dj * xs.y;
                    acc.z += dj * xs.z;
                    acc.w += dj * xs.w;
                }
            }
            acc.x *= dvp; acc.y *= dvp; acc.z *= dvp; acc.w *= dvp;
        }
        *(float4*)&sA[r * SA_S + lane * 4] = acc;
    }
    __syncthreads();

    ull acc2[8][2];
    #pragma unroll
    for (int i = 0; i < 8; i++) { acc2[i][0] = 0ull; acc2[i][1] = 0ull; }

    int tx = lane, ty = wid;

    for (int kk = 0; kk < DD; kk += 16) {
        for (int q = tid; q < 512; q += 256) {
            int k = q >> 5, c4 = (q & 31) * 4;
            *(float4*)&sB[k * 128 + c4] = *(const float4*)&W[(long)(kk + k) * DD + c4];
        }
        __syncthreads();
        #pragma unroll
        for (int k = 0; k < 16; k++) {
            float4 b4 = *(float4*)&sB[k * 128 + tx * 4];
            ull b01, b23;
            PACK2(b01, b4.x, b4.y);
            PACK2(b23, b4.z, b4.w);
            #pragma unroll
            for (int i = 0; i < 8; i++) {
                float a = sA[(ty * 8 + i) * SA_S + kk + k];
                ull aa;
                PACK2(aa, a, a);
                FMA_F32X2(acc2[i][0], aa, b01, acc2[i][0]);
                FMA_F32X2(acc2[i][1], aa, b23, acc2[i][1]);
            }
        }
        __syncthreads();
    }

    float4 bias = *(const float4*)&bfu[tx * 4];
    #pragma unroll
    for (int i = 0; i < 8; i++) {
        int r = ty * 8 + i;
        int grow = row0 + r;
        if (grow < BK) {
            float sc = g_selscore[grow];
            float v0, v1, v2, v3;
            UNPACK2(v0, v1, acc2[i][0]);
            UNPACK2(v2, v3, acc2[i][1]);
            v0 += bias.x; v1 += bias.y; v2 += bias.z; v3 += bias.w;
            long base = (long)grow * DD + tx * 4;
            *(float4*)&out[base] = make_float4(v0*sc, v1*sc, v2*sc, v3*sc);
            *(float2*)&out[xaeOff + base]     = make_float2(v0, v1);
            *(float2*)&out[xaeOff + base + 2] = make_float2(v2, v3);
        }
    }
}

#define SCAN_T 256
#define SCAN_I 8
#define SCAN_B ((EE + SCAN_T*SCAN_I - 1) / (SCAN_T*SCAN_I))

__global__ void k_flag(const int* __restrict__ src, const int* __restrict__ dst) {
    __shared__ int wsum[8];
    int tid = threadIdx.x;
    int base = blockIdx.x * SCAN_T * SCAN_I + tid * SCAN_I;
    int cnt = 0;
    #pragma unroll
    for (int t = 0; t < SCAN_I; t++) {
        int e = base + t;
        if (e < EE && g_nodemap[src[e]] >= 0 && g_nodemap[dst[e]] >= 0) cnt++;
    }
    int lane = tid & 31, wid = tid >> 5;
    int v = cnt;
    #pragma unroll
    for (int o = 16; o > 0; o >>= 1) v += __shfl_down_sync(0xffffffffu, v, o);
    if (lane == 0) wsum[wid] = v;
    __syncthreads();
    if (tid == 0) {
        int tot = 0;
        for (int w = 0; w < 8; w++) tot += wsum[w];
        g_bsum[blockIdx.x] = tot;
    }
}

__global__ void k_scan() {
    if (threadIdx.x == 0) {
        int run = 0;
        for (int b = 0; b < SCAN_B; b++) { g_boff[b] = run; run += g_bsum[b]; }
    }
}

__global__ void k_scatter(const int* __restrict__ src, const int* __restrict__ dst,
                          float* __restrict__ out, long edgeOff, int M) {
    __shared__ int wsum[8];
    __shared__ int woff[8];
    int tid = threadIdx.x;
    int base = blockIdx.x * SCAN_T * SCAN_I + tid * SCAN_I;
    int f[SCAN_I], r[SCAN_I], c[SCAN_I];
    int cnt = 0;
    #pragma unroll
    for (int t = 0; t < SCAN_I; t++) {
        int e = base + t;
        f[t] = 0;
        if (e < EE) {
            int rr = g_nodemap[src[e]];
            int cc = g_nodemap[dst[e]];
            if (rr >= 0 && cc >= 0) { f[t] = 1; r[t] = rr; c[t] = cc; cnt++; }
        }
    }
    int lane = tid & 31, wid = tid >> 5;
    int v = cnt;
    #pragma unroll
    for (int o = 1; o < 32; o <<= 1) {
        int u = __shfl_up_sync(0xffffffffu, v, o);
        if (lane >= o) v += u;
    }
    if (lane == 31) wsum[wid] = v;
    __syncthreads();
    if (tid == 0) {
        int run = 0;
        for (int w = 0; w < 8; w++) { woff[w] = run; run += wsum[w]; }
    }
    __syncthreads();
    int pos = (v - cnt) + woff[wid] + g_boff[blockIdx.x];
    #pragma unroll
    for (int t = 0; t < SCAN_I; t++) {
        if (f[t]) {
            out[edgeOff + pos]     = (float)r[t];
            out[edgeOff + M + pos] = (float)c[t];
            pos++;
        }
    }
}

struct AsyncRes {
    cudaStream_t s1, s2;
    cudaEvent_t evRoot, evScores, evMemset, evTopk, evTail;
    void *pDeg, *pSsacc, *pNodemap, *pTotal;
    AsyncRes() {
        cudaStreamCreateWithFlags(&s1, cudaStreamNonBlocking);
        cudaStreamCreateWithFlags(&s2, cudaStreamNonBlocking);
        cudaEventCreateWithFlags(&evRoot,   cudaEventDisableTiming);
        cudaEventCreateWithFlags(&evScores, cudaEventDisableTiming);
        cudaEventCreateWithFlags(&evMemset, cudaEventDisableTiming);
        cudaEventCreateWithFlags(&evTopk,   cudaEventDisableTiming);
        cudaEventCreateWithFlags(&evTail,   cudaEventDisableTiming);
        cudaGetSymbolAddress(&pDeg,     g_deg);
        cudaGetSymbolAddress(&pSsacc,   g_ssacc);
        cudaGetSymbolAddress(&pNodemap, g_nodemap);
        cudaGetSymbolAddress(&pTotal,   g_total);
    }
};

extern "C" void kernel_launch(void* const* d_in, const int* in_sizes, int n_in,
                              void* d_out, int out_size) {
    const float* x    = (const float*)d_in[0];
    const int*   ei   = (const int*)d_in[1];
    const float* Ws   = (const float*)d_in[3];
    const float* bs   = (const float*)d_in[4];
    const float* Wf   = (const float*)d_in[5];
    const float* bf   = (const float*)d_in[6];
    const float* Wfu  = (const float*)d_in[7];
    const float* bfu  = (const float*)d_in[8];
    float* out = (float*)d_out;

    static AsyncRes R;

    const int* src = ei;
    const int* dst = ei + EE;

    long M = ((long)out_size - (2L * BK * DD + 2L * BK)) / 2;
    long edgeOff  = (long)BK * DD;
    long batchOff = edgeOff + 2 * M;
    long permOff  = batchOff + BK;
    long xaeOff   = permOff + BK;

    // fork: score GEMVs on s1 (need only x/weights)
    cudaEventRecord(R.evRoot, 0);
    cudaStreamWaitEvent(R.s1, R.evRoot, 0);
    k_scores<<<(NN * 32 + 255) / 256, 256, 0, R.s1>>>(x, Ws, Wf, bf);
    cudaEventRecord(R.evScores, R.s1);

    // fork: non-deg memsets on s2
    cudaStreamWaitEvent(R.s2, R.evRoot, 0);
    cudaMemsetAsync(R.pSsacc,   0,    NN * sizeof(float), R.s2);
    cudaMemsetAsync(R.pNodemap, 0xFF, NN * sizeof(int),   R.s2);
    cudaMemsetAsync(R.pTotal,   0,    sizeof(int),        R.s2);
    cudaEventRecord(R.evMemset, R.s2);

    // main: deg memset + degree histogram
    cudaMemsetAsync(R.pDeg, 0, NN * sizeof(int), 0);
    k_deg<<<(EE / 4 + 255) / 256, 256>>>(dst);

    // join scores + memsets; offsets fuses dinv + zs + cursor seed
    cudaStreamWaitEvent(0, R.evScores, 0);
    cudaStreamWaitEvent(0, R.evMemset, 0);
    k_offsets<<<(NN + 255) / 256, 256>>>();

    // fused CSR build + score scatter (single edge pass)
    k_csr_score<<<(EE / 4 + 255) / 256, 256>>>(src, dst);

    // fused score finalize + topk
    k_topk<<<BB * 4, 256>>>(bs, out, permOff, batchOff);

    // fork: edge compaction on s1 (needs nodemap only)
    cudaEventRecord(R.evTopk, 0);
    cudaStreamWaitEvent(R.s1, R.evTopk, 0);
    k_flag<<<SCAN_B, SCAN_T, 0, R.s1>>>(src, dst);
    k_scan<<<1, 32, 0, R.s1>>>();
    k_scatter<<<SCAN_B, SCAN_T, 0, R.s1>>>(src, dst, out, edgeOff, (int)M);
    cudaEventRecord(R.evTail, R.s1);

    // main: fused gather + GEMM
    k_gemm<<<(BK + 63) / 64, 256>>>(x, Wfu, bfu, out, xaeOff);

    cudaStreamWaitEvent(0, R.evTail, 0);
}

// round 13
// speedup vs baseline: 1.0444x; 1.0444x over previous
#include <cuda_runtime.h>
#include <math.h>

#define NN   50000
#define EE   500000
#define DD   128
#define BB   50
#define NPG  1000
#define KSEL 500
#define BK   (BB*KSEL)
#define ALPHA_F 0.6f
#define MKB  296      // 2 blocks/SM on >=148 SMs: single wave, residency guaranteed

typedef unsigned long long ull;

#define FMA_F32X2(d, a, b, c) \
    asm("fma.rn.f32x2 %0, %1, %2, %3;" : "=l"(d) : "l"(a), "l"(b), "l"(c))
#define PACK2(d, lo, hi) \
    asm("mov.b64 %0, {%1, %2};" : "=l"(d) : "f"(lo), "f"(hi))
#define UNPACK2(lo, hi, s) \
    asm("mov.b64 {%0, %1}, %2;" : "=f"(lo), "=f"(hi) : "l"(s))

__device__ int   g_deg[NN];
__device__ float g_dinv[NN];
__device__ float g_ds[NN];
__device__ float g_zs[NN];
__device__ float g_sf[NN];
__device__ float g_ssacc[NN];
__device__ int   g_perm[BK];
__device__ float g_selscore[BK];
__device__ int   g_nodemap[NN];
__device__ int   g_off[NN];
__device__ int   g_cursor[NN];
__device__ int   g_csr[EE];
__device__ int   g_total;
__device__ int   g_bsum[512];
__device__ int   g_boff[512];

// ---------------- software grid barrier (all MKB blocks resident) ----------------
__device__ unsigned          g_arrive;   // zero-init; self-resetting
__device__ volatile unsigned g_gen;      // generation counter (monotonic across replays)

__device__ __forceinline__ void gbar() {
    __threadfence();          // release this thread's prior writes
    __syncthreads();
    if (threadIdx.x == 0) {
        unsigned gen = g_gen;
        if (atomicAdd(&g_arrive, 1u) == gridDim.x - 1u) {
            g_arrive = 0u;
            __threadfence();
            g_gen = gen + 1u;
        } else {
            while (g_gen == gen) __nanosleep(64);
        }
        __threadfence();      // acquire
    }
    __syncthreads();
}

// ---------------- megakernel: init -> scores+deg -> offsets -> csr+score -> topk ----
__global__ void __launch_bounds__(256, 2)
k_mega(const float* __restrict__ x,  const float* __restrict__ Ws,
       const float* __restrict__ Wf, const float* __restrict__ bf,
       const float* __restrict__ bs,
       const int* __restrict__ src,  const int* __restrict__ dst,
       float* __restrict__ out, long permOff, long batchOff) {
    __shared__ __align__(16) ull sk[NPG];   // 8 KB (topk phase)
    __shared__ float ssc[NPG];              // 4 KB
    __shared__ int wpref[8];

    int tid  = threadIdx.x;
    int gtid = blockIdx.x * 256 + tid;
    int gsz  = gridDim.x * 256;
    int lane = tid & 31;

    // ---- P0: init scratch ----
    for (int t = gtid; t < NN; t += gsz) {
        g_deg[t] = 0;
        g_ssacc[t] = 0.f;
        g_nodemap[t] = -1;
    }
    if (gtid == 0) g_total = 0;
    gbar();

    // ---- P1: per-node score GEMVs (warp/node, 2-way unroll) + degree histogram ----
    {
        float4 wsv = ((const float4*)Ws)[lane];
        float4 wfv = ((const float4*)Wf)[lane];
        float bf0 = bf[0];
        int gw = gtid >> 5;
        int nw = gsz >> 5;
        for (int n = gw; n < NN; n += 2 * nw) {
            int n1 = n + nw;
            float4 x0 = ((const float4*)x)[n * 32 + lane];
            float4 x1 = (n1 < NN) ? ((const float4*)x)[n1 * 32 + lane]
                                  : make_float4(0.f, 0.f, 0.f, 0.f);
            float a0 = x0.x*wsv.x + x0.y*wsv.y + x0.z*wsv.z + x0.w*wsv.w;
            float b0 = x0.x*wfv.x + x0.y*wfv.y + x0.z*wfv.z + x0.w*wfv.w;
            float a1 = x1.x*wsv.x + x1.y*wsv.y + x1.z*wsv.z + x1.w*wsv.w;
            float b1 = x1.x*wfv.x + x1.y*wfv.y + x1.z*wfv.z + x1.w*wfv.w;
            #pragma unroll
            for (int o = 16; o > 0; o >>= 1) {
                a0 += __shfl_down_sync(0xffffffffu, a0, o);
                b0 += __shfl_down_sync(0xffffffffu, b0, o);
                a1 += __shfl_down_sync(0xffffffffu, a1, o);
                b1 += __shfl_down_sync(0xffffffffu, b1, o);
            }
            if (lane == 0) {
                g_ds[n] = a0;
                g_sf[n] = b0 + bf0;
                if (n1 < NN) { g_ds[n1] = a1; g_sf[n1] = b1 + bf0; }
            }
        }
        for (int t = gtid; t < EE / 4; t += gsz) {
            int4 d4 = ((const int4*)dst)[t];
            atomicAdd(&g_deg[d4.x], 1);
            atomicAdd(&g_deg[d4.y], 1);
            atomicAdd(&g_deg[d4.z], 1);
            atomicAdd(&g_deg[d4.w], 1);
        }
    }
    gbar();

    // ---- P2: offsets (block scan + one atomic), dinv, zs, cursor seed ----
    for (int tile = blockIdx.x; tile < (NN + 255) / 256; tile += gridDim.x) {
        int n = tile * 256 + tid;
        int d = (n < NN) ? g_deg[n] : 0;
        int wid = tid >> 5;
        int v = d;
        #pragma unroll
        for (int o = 1; o < 32; o <<= 1) {
            int u = __shfl_up_sync(0xffffffffu, v, o);
            if (lane >= o) v += u;
        }
        if (lane == 31) wpref[wid] = v;
        __syncthreads();
        if (tid == 0) {
            int t[8], run = 0;
            #pragma unroll
            for (int w = 0; w < 8; w++) { t[w] = run; run += wpref[w]; }
            int base = atomicAdd(&g_total, run);
            #pragma unroll
            for (int w = 0; w < 8; w++) wpref[w] = base + t[w];
        }
        __syncthreads();
        int off = wpref[wid] + (v - d);
        if (n < NN) {
            g_off[n]    = off;
            g_cursor[n] = off;
            float dv = rsqrtf((float)(d + 1));
            g_dinv[n] = dv;
            g_zs[n]   = dv * g_ds[n];
        }
        __syncthreads();
    }
    gbar();

    // ---- P3: fused CSR scatter + structure-score scatter ----
    for (int t = gtid; t < EE / 4; t += gsz) {
        int4 s4 = ((const int4*)src)[t];
        int4 d4 = ((const int4*)dst)[t];
        g_csr[atomicAdd(&g_cursor[d4.x], 1)] = s4.x;
        g_csr[atomicAdd(&g_cursor[d4.y], 1)] = s4.y;
        g_csr[atomicAdd(&g_cursor[d4.z], 1)] = s4.z;
        g_csr[atomicAdd(&g_cursor[d4.w], 1)] = s4.w;
        atomicAdd(&g_ssacc[d4.x], g_zs[s4.x]);
        atomicAdd(&g_ssacc[d4.y], g_zs[s4.y]);
        atomicAdd(&g_ssacc[d4.z], g_zs[s4.z]);
        atomicAdd(&g_ssacc[d4.w], g_zs[s4.w]);
    }
    gbar();

    // ---- P4: score finalize (tanh) + per-graph rank selection (4 tiles/graph) ----
    {
        float bsv = bs[0];
        for (int tile = blockIdx.x; tile < BB * 4; tile += gridDim.x) {
            int b = tile >> 2;
            int quarter = tile & 3;
            for (int i = tid; i < NPG; i += 256) {
                int n = b * NPG + i;
                float ss = g_dinv[n] * (g_ssacc[n] + g_zs[n]) + bsv;
                float sc = tanhf(ALPHA_F * ss + (1.0f - ALPHA_F) * g_sf[n]);
                ssc[i] = sc;
                int iv = __float_as_int(sc);
                unsigned u = (unsigned)iv ^ ((unsigned)(iv >> 31) | 0x80000000u);
                sk[i] = ((ull)u << 32) | (unsigned)(~i);
            }
            __syncthreads();
            int j = quarter * 256 + tid;
            if (j < NPG) {
                ull myk = sk[j];
                int rank = 0;
                const ulonglong2* p2 = (const ulonglong2*)sk;
                #pragma unroll 4
                for (int i2 = 0; i2 < NPG / 2; i2++) {
                    ulonglong2 kv = p2[i2];
                    rank += (kv.x > myk);
                    rank += (kv.y > myk);
                }
                if (rank < KSEL) {
                    int p  = b * NPG + j;
                    int gi = b * KSEL + rank;
                    g_perm[gi]     = p;
                    g_selscore[gi] = ssc[j];
                    g_nodemap[p]   = gi;
                    out[permOff  + gi] = (float)p;
                    out[batchOff + gi] = (float)b;
                }
            }
            __syncthreads();
        }
    }
}

// ---------------- fused gather + FMA2 GEMM (unchanged from 90.2-passing R10) --------
#define SA_S 132
__global__ void __launch_bounds__(256)
k_gemm(const float* __restrict__ x, const float* __restrict__ W,
       const float* __restrict__ bfu, float* __restrict__ out, long xaeOff) {
    __shared__ __align__(16) float sA[64 * SA_S];   // 33.8 KB
    __shared__ __align__(16) float sB[16 * 128];    // 8 KB

    int tid  = threadIdx.x;
    int lane = tid & 31, wid = tid >> 5;
    int row0 = blockIdx.x * 64;

    #pragma unroll
    for (int i = 0; i < 8; i++) {
        int r = wid * 8 + i;
        int grow = row0 + r;
        float4 acc = make_float4(0.f, 0.f, 0.f, 0.f);
        if (grow < BK) {
            int   p   = g_perm[grow];
            float dvp = g_dinv[p];
            float4 xv = ((const float4*)x)[p * 32 + lane];
            acc = make_float4(dvp*xv.x, dvp*xv.y, dvp*xv.z, dvp*xv.w);
            int beg = g_off[p], len = g_deg[p];
            for (int base = 0; base < len; base += 32) {
                int idx = base + lane;
                int   s  = (idx < len) ? g_csr[beg + idx] : 0;
                float dv = (idx < len) ? g_dinv[s] : 0.f;
                int cnt = min(32, len - base);
                for (int j = 0; j < cnt; j++) {
                    int   sj = __shfl_sync(0xffffffffu, s,  j);
                    float dj = __shfl_sync(0xffffffffu, dv, j);
                    float4 xs = ((const float4*)x)[sj * 32 + lane];
                    acc.x += dj * xs.x;
                    acc.y += dj * xs.y;
                    acc.z += dj * xs.z;
                    acc.w += dj * xs.w;
                }
            }
            acc.x *= dvp; acc.y *= dvp; acc.z *= dvp; acc.w *= dvp;
        }
        *(float4*)&sA[r * SA_S + lane * 4] = acc;
    }
    __syncthreads();

    ull acc2[8][2];
    #pragma unroll
    for (int i = 0; i < 8; i++) { acc2[i][0] = 0ull; acc2[i][1] = 0ull; }

    int tx = lane, ty = wid;

    for (int kk = 0; kk < DD; kk += 16) {
        for (int q = tid; q < 512; q += 256) {
            int k = q >> 5, c4 = (q & 31) * 4;
            *(float4*)&sB[k * 128 + c4] = *(const float4*)&W[(long)(kk + k) * DD + c4];
        }
        __syncthreads();
        #pragma unroll
        for (int k = 0; k < 16; k++) {
            float4 b4 = *(float4*)&sB[k * 128 + tx * 4];
            ull b01, b23;
            PACK2(b01, b4.x, b4.y);
            PACK2(b23, b4.z, b4.w);
            #pragma unroll
            for (int i = 0; i < 8; i++) {
                float a = sA[(ty * 8 + i) * SA_S + kk + k];
                ull aa;
                PACK2(aa, a, a);
                FMA_F32X2(acc2[i][0], aa, b01, acc2[i][0]);
                FMA_F32X2(acc2[i][1], aa, b23, acc2[i][1]);
            }
        }
        __syncthreads();
    }

    float4 bias = *(const float4*)&bfu[tx * 4];
    #pragma unroll
    for (int i = 0; i < 8; i++) {
        int r = ty * 8 + i;
        int grow = row0 + r;
        if (grow < BK) {
            float sc = g_selscore[grow];
            float v0, v1, v2, v3;
            UNPACK2(v0, v1, acc2[i][0]);
            UNPACK2(v2, v3, acc2[i][1]);
            v0 += bias.x; v1 += bias.y; v2 += bias.z; v3 += bias.w;
            long base = (long)grow * DD + tx * 4;
            *(float4*)&out[base] = make_float4(v0*sc, v1*sc, v2*sc, v3*sc);
            *(float2*)&out[xaeOff + base]     = make_float2(v0, v1);
            *(float2*)&out[xaeOff + base + 2] = make_float2(v2, v3);
        }
    }
}

// ---------------- stable edge compaction (forked; hidden under GEMM) ----------------
#define SCAN_T 256
#define SCAN_I 8
#define SCAN_B ((EE + SCAN_T*SCAN_I - 1) / (SCAN_T*SCAN_I))

__global__ void k_flag(const int* __restrict__ src, const int* __restrict__ dst) {
    __shared__ int wsum[8];
    int tid = threadIdx.x;
    int base = blockIdx.x * SCAN_T * SCAN_I + tid * SCAN_I;
    int cnt = 0;
    #pragma unroll
    for (int t = 0; t < SCAN_I; t++) {
        int e = base + t;
        if (e < EE && g_nodemap[src[e]] >= 0 && g_nodemap[dst[e]] >= 0) cnt++;
    }
    int lane = tid & 31, wid = tid >> 5;
    int v = cnt;
    #pragma unroll
    for (int o = 16; o > 0; o >>= 1) v += __shfl_down_sync(0xffffffffu, v, o);
    if (lane == 0) wsum[wid] = v;
    __syncthreads();
    if (tid == 0) {
        int tot = 0;
        for (int w = 0; w < 8; w++) tot += wsum[w];
        g_bsum[blockIdx.x] = tot;
    }
}

__global__ void k_scan() {
    if (threadIdx.x == 0) {
        int run = 0;
        for (int b = 0; b < SCAN_B; b++) { g_boff[b] = run; run += g_bsum[b]; }
    }
}

__global__ void k_scatter(const int* __restrict__ src, const int* __restrict__ dst,
                          float* __restrict__ out, long edgeOff, int M) {
    __shared__ int wsum[8];
    __shared__ int woff[8];
    int tid = threadIdx.x;
    int base = blockIdx.x * SCAN_T * SCAN_I + tid * SCAN_I;
    int f[SCAN_I], r[SCAN_I], c[SCAN_I];
    int cnt = 0;
    #pragma unroll
    for (int t = 0; t < SCAN_I; t++) {
        int e = base + t;
        f[t] = 0;
        if (e < EE) {
            int rr = g_nodemap[src[e]];
            int cc = g_nodemap[dst[e]];
            if (rr >= 0 && cc >= 0) { f[t] = 1; r[t] = rr; c[t] = cc; cnt++; }
        }
    }
    int lane = tid & 31, wid = tid >> 5;
    int v = cnt;
    #pragma unroll
    for (int o = 1; o < 32; o <<= 1) {
        int u = __shfl_up_sync(0xffffffffu, v, o);
        if (lane >= o) v += u;
    }
    if (lane == 31) wsum[wid] = v;
    __syncthreads();
    if (tid == 0) {
        int run = 0;
        for (int w = 0; w < 8; w++) { woff[w] = run; run += wsum[w]; }
    }
    __syncthreads();
    int pos = (v - cnt) + woff[wid] + g_boff[blockIdx.x];
    #pragma unroll
    for (int t = 0; t < SCAN_I; t++) {
        if (f[t]) {
            out[edgeOff + pos]     = (float)r[t];
            out[edgeOff + M + pos] = (float)c[t];
            pos++;
        }
    }
}

struct AsyncRes {
    cudaStream_t s1;
    cudaEvent_t evTopk, evTail;
    AsyncRes() {
        cudaStreamCreateWithFlags(&s1, cudaStreamNonBlocking);
        cudaEventCreateWithFlags(&evTopk, cudaEventDisableTiming);
        cudaEventCreateWithFlags(&evTail, cudaEventDisableTiming);
    }
};

extern "C" void kernel_launch(void* const* d_in, const int* in_sizes, int n_in,
                              void* d_out, int out_size) {
    const float* x    = (const float*)d_in[0];
    const int*   ei   = (const int*)d_in[1];
    const float* Ws   = (const float*)d_in[3];
    const float* bs   = (const float*)d_in[4];
    const float* Wf   = (const float*)d_in[5];
    const float* bf   = (const float*)d_in[6];
    const float* Wfu  = (const float*)d_in[7];
    const float* bfu  = (const float*)d_in[8];
    float* out = (float*)d_out;

    static AsyncRes R;

    const int* src = ei;
    const int* dst = ei + EE;

    long M = ((long)out_size - (2L * BK * DD + 2L * BK)) / 2;
    long edgeOff  = (long)BK * DD;
    long batchOff = edgeOff + 2 * M;
    long permOff  = batchOff + BK;
    long xaeOff   = permOff + BK;

    // single persistent megakernel: init -> scores+deg -> offsets -> csr/score -> topk
    k_mega<<<MKB, 256>>>(x, Ws, Wf, bf, bs, src, dst, out, permOff, batchOff);

    // fork: edge compaction tail on s1 (needs nodemap only), hidden under GEMM
    cudaEventRecord(R.evTopk, 0);
    cudaStreamWaitEvent(R.s1, R.evTopk, 0);
    k_flag<<<SCAN_B, SCAN_T, 0, R.s1>>>(src, dst);
    k_scan<<<1, 32, 0, R.s1>>>();
    k_scatter<<<SCAN_B, SCAN_T, 0, R.s1>>>(src, dst, out, edgeOff, (int)M);
    cudaEventRecord(R.evTail, R.s1);

    // main: fused gather + GEMM
    k_gemm<<<(BK + 63) / 64, 256>>>(x, Wfu, bfu, out, xaeOff);

    cudaStreamWaitEvent(0, R.evTail, 0);
}